// round 16
// baseline (speedup 1.0000x reference)
#include <cuda_runtime.h>
#include <cuda_bf16.h>
#include <cuda_fp16.h>

// Problem constants
#define NN 100000
#define NE 1600000
#define IN_CH 128
#define EDGE_CH 32
#define HEADS 4
#define OUT_CH 32
#define HC 128            // HEADS*OUT_CH
#define NEG_SLOPE 0.2f
#define EPS 1e-16f
#define CAP 80            // max in-degree bucket capacity (Poisson(16): P(>=80)~1e-28)

typedef unsigned long long u64;
typedef long long ll;

// Scratch (device globals — allocation-free)
__device__ uint2 g_xh[(size_t)NN * 32];            // projected node features, fp16x4 packed [N,128]
__device__ float g_al[NN * HEADS];                 // alpha_l per node
__device__ float g_ar[NN * HEADS];                 // alpha_r per node
__device__ int   g_cnt[NN];                        // in-degree counters
__device__ int   g_bsrc[(size_t)NN * CAP];         // bucketed src ids
__device__ float g_bex[(size_t)NN * CAP * HEADS];  // bucketed exp(logit) per head
__device__ float g_u[2 * HEADS * IN_CH];           // folded att_l/att_r through Wl
__device__ float g_v[HEADS * EDGE_CH];             // folded att_e through We

// ---- packed fp32x2 helpers ----
__device__ __forceinline__ u64 pack_dup(float a) {
    u64 r; asm("mov.b64 %0,{%1,%1};" : "=l"(r) : "f"(a)); return r;
}
__device__ __forceinline__ void ffma2(u64& d, u64 a, u64 b) {
    asm("fma.rn.f32x2 %0, %1, %2, %0;" : "+l"(d) : "l"(a), "l"(b));
}
__device__ __forceinline__ float2 unpk(u64 v) {
    float2 f; asm("mov.b64 {%0,%1}, %2;" : "=f"(f.x), "=f"(f.y) : "l"(v)); return f;
}

// ---------------------------------------------------------------------------
// K0: fold attention vectors through the weight matrices.
// ---------------------------------------------------------------------------
__global__ void k0_fold(const float* __restrict__ Wl, const float* __restrict__ We,
                        const float* __restrict__ att_l, const float* __restrict__ att_r,
                        const float* __restrict__ att_e) {
    int t = threadIdx.x;
    for (int i = t; i < 2 * HEADS * IN_CH; i += blockDim.x) {
        int side = i / (HEADS * IN_CH);
        int rem = i % (HEADS * IN_CH);
        int h = rem / IN_CH;
        int k = rem % IN_CH;
        const float* att = side ? att_r : att_l;
        float s = 0.f;
        #pragma unroll
        for (int c = 0; c < OUT_CH; c++)
            s += att[h * OUT_CH + c] * Wl[(h * OUT_CH + c) * IN_CH + k];
        g_u[i] = s;
    }
    for (int i = t; i < HEADS * EDGE_CH; i += blockDim.x) {
        int h = i / EDGE_CH;
        int ec = i % EDGE_CH;
        float s = 0.f;
        #pragma unroll
        for (int c = 0; c < OUT_CH; c++)
            s += att_e[h * OUT_CH + c] * We[(h * OUT_CH + c) * EDGE_CH + ec];
        g_v[i] = s;
    }
}

// ---------------------------------------------------------------------------
// KALR: alpha_l/alpha_r via folded u. 8-lane groups, 4 nodes per warp,
// 32 nodes per block, grid = NN/32 = 3125. Also zeros g_cnt.
// ---------------------------------------------------------------------------
__global__ void kalr(const float* __restrict__ x) {
    __shared__ float su[2 * HEADS * IN_CH];   // 1024 floats
    int t = threadIdx.x;
    for (int i = t; i < 1024; i += 256) su[i] = g_u[i];
    if (blockIdx.x < 391) {
        int zi = blockIdx.x * 256 + t;
        if (zi < NN) g_cnt[zi] = 0;
    }
    __syncthreads();

    int warp = t >> 5, lane = t & 31;
    int g = lane >> 3, l8 = lane & 7;
    int node = blockIdx.x * 32 + warp * 4 + g;   // 3125*32 = 100000 exact

    const float4* x4 = (const float4*)x;
    float p[8];
    #pragma unroll
    for (int o = 0; o < 8; o++) p[o] = 0.f;

    #pragma unroll
    for (int c = 0; c < 4; c++) {
        float4 xv = x4[(ll)node * 32 + c * 8 + l8];
        #pragma unroll
        for (int o = 0; o < 8; o++) {
            const float* u = su + o * IN_CH + c * 32 + l8 * 4;
            p[o] += xv.x * u[0] + xv.y * u[1] + xv.z * u[2] + xv.w * u[3];
        }
    }
    #pragma unroll
    for (int o = 0; o < 8; o++) {
        p[o] += __shfl_xor_sync(0xFFFFFFFF, p[o], 1);
        p[o] += __shfl_xor_sync(0xFFFFFFFF, p[o], 2);
        p[o] += __shfl_xor_sync(0xFFFFFFFF, p[o], 4);
    }
    int o = l8;
    float val = p[o];
    int side = o >> 2, h = o & 3;
    if (side == 0) g_al[node * HEADS + h] = val;
    else           g_ar[node * HEADS + h] = val;
}

// ---------------------------------------------------------------------------
// K1: xl = x @ Wl^T, 64 rows/block, 256 threads, 8x4 tile, f32x2 FMA.
// W tile held in smem as fp16 (halves smem -> 3 CTAs/SM). x tile fp32.
// Output stored as packed fp16 (only consumer is the k5 gather).
// ---------------------------------------------------------------------------
#define XSTRIDE 68    // 64 + 4 pad: 4-way store conflicts (one-time), 16B-aligned rows

__global__ void k1_gemm(const float* __restrict__ x, const float* __restrict__ Wl) {
    extern __shared__ float sm[];
    __half* sWh = (__half*)sm;               // [k][j] : 128x128 halves (32KB)
    float* sxT = sm + 8192;                  // [k][r] stride XSTRIDE (34.8KB)

    int t = threadIdx.x;
    int row0 = blockIdx.x * 64;

    // Load Wl transposed into fp16 smem (coalesced gmem read)
    for (int i = t; i < IN_CH * IN_CH; i += 256) {
        int j = i >> 7, k = i & 127;
        sWh[k * IN_CH + j] = __float2half(Wl[i]);
    }
    // Load 64 x-rows transposed (clamped for the partial last block)
    for (int i = t; i < 64 * IN_CH; i += 256) {
        int r = i >> 7, k = i & 127;
        int rr = row0 + r; rr = rr < NN ? rr : NN - 1;
        sxT[k * XSTRIDE + r] = x[(ll)rr * IN_CH + k];
    }
    __syncthreads();

    int rg = t >> 5;
    int cg = t & 31;

    u64 acc[4][4];
    #pragma unroll
    for (int i = 0; i < 4; i++)
        #pragma unroll
        for (int j = 0; j < 4; j++) acc[i][j] = 0ull;

    const float* xbase = sxT + rg * 8;
    const __half* wbase = sWh + cg * 4;

    #pragma unroll 4
    for (int k = 0; k < IN_CH; k++) {
        ulonglong2 xa = *(const ulonglong2*)(xbase + k * XSTRIDE);
        ulonglong2 xb = *(const ulonglong2*)(xbase + k * XSTRIDE + 4);
        uint2 wu = *(const uint2*)(wbase + k * IN_CH);      // 4 halves
        float2 f01 = __half22float2(*(__half2*)&wu.x);
        float2 f23 = __half22float2(*(__half2*)&wu.y);
        u64 w0 = pack_dup(f01.x), w1 = pack_dup(f01.y);
        u64 w2 = pack_dup(f23.x), w3 = pack_dup(f23.y);
        ffma2(acc[0][0], xa.x, w0); ffma2(acc[0][1], xa.x, w1);
        ffma2(acc[0][2], xa.x, w2); ffma2(acc[0][3], xa.x, w3);
        ffma2(acc[1][0], xa.y, w0); ffma2(acc[1][1], xa.y, w1);
        ffma2(acc[1][2], xa.y, w2); ffma2(acc[1][3], xa.y, w3);
        ffma2(acc[2][0], xb.x, w0); ffma2(acc[2][1], xb.x, w1);
        ffma2(acc[2][2], xb.x, w2); ffma2(acc[2][3], xb.x, w3);
        ffma2(acc[3][0], xb.y, w0); ffma2(acc[3][1], xb.y, w1);
        ffma2(acc[3][2], xb.y, w2); ffma2(acc[3][3], xb.y, w3);
    }

    #pragma unroll
    for (int rp = 0; rp < 4; rp++) {
        float2 a0 = unpk(acc[rp][0]), a1 = unpk(acc[rp][1]);
        float2 a2 = unpk(acc[rp][2]), a3 = unpk(acc[rp][3]);
        int rA = row0 + rg * 8 + rp * 2;
        union { uint2 u; __half2 h[2]; } P;
        if (rA < NN) {
            P.h[0] = __floats2half2_rn(a0.x, a1.x);
            P.h[1] = __floats2half2_rn(a2.x, a3.x);
            g_xh[(ll)rA * 32 + cg] = P.u;
        }
        if (rA + 1 < NN) {
            P.h[0] = __floats2half2_rn(a0.y, a1.y);
            P.h[1] = __floats2half2_rn(a2.y, a3.y);
            g_xh[(ll)(rA + 1) * 32 + cg] = P.u;
        }
    }
}

// ---------------------------------------------------------------------------
// K2F: fused edge kernel. 2 lanes stream one edge's 32 channels (coalesced),
// shfl reduce, then the even lane assembles the logit, exp, and buckets it.
// ---------------------------------------------------------------------------
__global__ void k2f_edge(const float* __restrict__ edge_attr,
                         const int* __restrict__ ei) {
    __shared__ float sv[HEADS * EDGE_CH];
    int t = threadIdx.x;
    if (t < HEADS * EDGE_CH) sv[t] = g_v[t];
    __syncthreads();

    int eg  = t >> 1;
    int sub = t & 1;
    int e = blockIdx.x * 128 + eg;

    int src = 0, dst = 0;
    if (sub == 0) { src = ei[e]; dst = ei[NE + e]; }

    const float4* ea = (const float4*)edge_attr;
    ll base = (ll)e * 8 + sub * 4;
    float4 v0 = ea[base + 0];
    float4 v1 = ea[base + 1];
    float4 v2 = ea[base + 2];
    float4 v3 = ea[base + 3];

    float acc[HEADS];
    #pragma unroll
    for (int h = 0; h < HEADS; h++) {
        const float* s = sv + h * EDGE_CH + sub * 16;
        float a;
        a  = v0.x * s[0]  + v0.y * s[1]  + v0.z * s[2]  + v0.w * s[3];
        a += v1.x * s[4]  + v1.y * s[5]  + v1.z * s[6]  + v1.w * s[7];
        a += v2.x * s[8]  + v2.y * s[9]  + v2.z * s[10] + v2.w * s[11];
        a += v3.x * s[12] + v3.y * s[13] + v3.z * s[14] + v3.w * s[15];
        acc[h] = a;
    }
    #pragma unroll
    for (int h = 0; h < HEADS; h++)
        acc[h] += __shfl_xor_sync(0xFFFFFFFF, acc[h], 1);

    if (sub == 0) {
        float4 av = ((const float4*)g_al)[src];
        float4 bv = ((const float4*)g_ar)[dst];
        float t0 = acc[0] + av.x + bv.x;
        float t1 = acc[1] + av.y + bv.y;
        float t2 = acc[2] + av.z + bv.z;
        float t3 = acc[3] + av.w + bv.w;
        t0 = fmaxf(t0, 0.f) + NEG_SLOPE * fminf(t0, 0.f);
        t1 = fmaxf(t1, 0.f) + NEG_SLOPE * fminf(t1, 0.f);
        t2 = fmaxf(t2, 0.f) + NEG_SLOPE * fminf(t2, 0.f);
        t3 = fmaxf(t3, 0.f) + NEG_SLOPE * fminf(t3, 0.f);
        float4 ex = make_float4(__expf(t0), __expf(t1), __expf(t2), __expf(t3));

        int pos = atomicAdd(&g_cnt[dst], 1);
        if (pos < CAP) {
            ll b = (ll)dst * CAP + pos;
            g_bsrc[b] = src;
            ((float4*)g_bex)[b] = ex;
        }
    }
}

// ---------------------------------------------------------------------------
// K5: 4 warps per node (quarter buckets), chunk-4 unroll, smem combine.
// 256 threads = 8 warps = 2 nodes/block; grid = NN/2 = 50000 exact.
// ---------------------------------------------------------------------------
__global__ void k5_agg(float* __restrict__ out, const float* __restrict__ bias) {
    __shared__ float sred[2][3][32][5];   // [node][warp-1][lane][5 partials]
    int t = threadIdx.x;
    int warp = t >> 5;
    int nodeL = warp >> 2;
    int sub = warp & 3;
    int node = blockIdx.x * 2 + nodeL;    // 50000*2 = 100000 exact
    int lane = t & 31;
    int h = lane >> 3;

    int cnt = min(g_cnt[node], CAP);
    int lo = (cnt * sub) >> 2;
    int hi = (cnt * (sub + 1)) >> 2;

    const int* bsrc = g_bsrc + (ll)node * CAP;
    const float* bex = g_bex + (ll)node * CAP * HEADS;

    float den = 0.f;
    float ax = 0.f, ay = 0.f, az = 0.f, aw = 0.f;

    int i = lo;
    for (; i + 4 <= hi; i += 4) {
        int s[4]; float w[4]; uint2 xv[4];
        #pragma unroll
        for (int j = 0; j < 4; j++) s[j] = bsrc[i + j];
        #pragma unroll
        for (int j = 0; j < 4; j++) w[j] = bex[(i + j) * HEADS + h];
        #pragma unroll
        for (int j = 0; j < 4; j++) xv[j] = g_xh[(ll)s[j] * 32 + lane];
        #pragma unroll
        for (int j = 0; j < 4; j++) {
            __half2* hp = (__half2*)&xv[j];
            float2 f01 = __half22float2(hp[0]);
            float2 f23 = __half22float2(hp[1]);
            den += w[j];
            ax += w[j] * f01.x; ay += w[j] * f01.y;
            az += w[j] * f23.x; aw += w[j] * f23.y;
        }
    }
    for (; i < hi; i++) {
        int s = bsrc[i];
        float w = bex[i * HEADS + h];
        uint2 xv = g_xh[(ll)s * 32 + lane];
        __half2* hp = (__half2*)&xv;
        float2 f01 = __half22float2(hp[0]);
        float2 f23 = __half22float2(hp[1]);
        den += w;
        ax += w * f01.x; ay += w * f01.y; az += w * f23.x; aw += w * f23.y;
    }

    if (sub) {
        float* r = sred[nodeL][sub - 1][lane];
        r[0] = den; r[1] = ax; r[2] = ay; r[3] = az; r[4] = aw;
    }
    __syncthreads();
    if (sub == 0) {
        #pragma unroll
        for (int p = 0; p < 3; p++) {
            const float* r = sred[nodeL][p][lane];
            den += r[0]; ax += r[1]; ay += r[2]; az += r[3]; aw += r[4];
        }
        float inv = 1.f / (den + EPS);
        float4 b = ((const float4*)bias)[lane];
        float4 o = make_float4(ax * inv + b.x, ay * inv + b.y,
                               az * inv + b.z, aw * inv + b.w);
        ((float4*)out)[(ll)node * 32 + lane] = o;
    }
}

// ---------------------------------------------------------------------------
extern "C" void kernel_launch(void* const* d_in, const int* in_sizes, int n_in,
                              void* d_out, int out_size) {
    const float* x        = (const float*)d_in[0];
    const float* edge_attr= (const float*)d_in[1];
    const float* Wl       = (const float*)d_in[2];
    const float* We       = (const float*)d_in[3];
    const float* att_l    = (const float*)d_in[4];
    const float* att_r    = (const float*)d_in[5];
    const float* att_e    = (const float*)d_in[6];
    const float* bias     = (const float*)d_in[7];
    const int*   ei       = (const int*)d_in[8];
    float* out = (float*)d_out;

    const int k1_smem = 8192 * 4 + IN_CH * XSTRIDE * 4;   // fp16 W + fp32 x = 67.6KB
    static cudaStream_t s1 = nullptr;
    static cudaEvent_t evFork = nullptr, evJoin = nullptr;
    if (!s1) {
        cudaFuncSetAttribute(k1_gemm, cudaFuncAttributeMaxDynamicSharedMemorySize, k1_smem);
        cudaStreamCreateWithFlags(&s1, cudaStreamNonBlocking);
        cudaEventCreateWithFlags(&evFork, cudaEventDisableTiming);
        cudaEventCreateWithFlags(&evJoin, cudaEventDisableTiming);
    }

    // default: k1 ----------------------------------------\
    //                                                      join -> k5
    // s1:      k0 -> kalr -> k2f -------------------------/
    cudaEventRecord(evFork, 0);
    cudaStreamWaitEvent(s1, evFork, 0);
    k0_fold<<<1, 256, 0, s1>>>(Wl, We, att_l, att_r, att_e);
    kalr<<<NN / 32, 256, 0, s1>>>(x);                      // al/ar + zero g_cnt
    k2f_edge<<<NE / 128, 256, 0, s1>>>(edge_attr, ei);
    cudaEventRecord(evJoin, s1);
    k1_gemm<<<(NN + 63) / 64, 256, k1_smem>>>(x, Wl);
    cudaStreamWaitEvent((cudaStream_t)0, evJoin, 0);
    k5_agg<<<NN / 2, 256>>>(out, bias);
}

// round 17
// speedup vs baseline: 1.8742x; 1.8742x over previous
#include <cuda_runtime.h>
#include <cuda_bf16.h>
#include <cuda_fp16.h>

// Problem constants
#define NN 100000
#define NE 1600000
#define IN_CH 128
#define EDGE_CH 32
#define HEADS 4
#define OUT_CH 32
#define HC 128            // HEADS*OUT_CH
#define NEG_SLOPE 0.2f
#define EPS 1e-16f
#define CAP 80            // max in-degree bucket capacity (Poisson(16): P(>=80)~1e-28)

typedef unsigned long long u64;
typedef long long ll;

// Scratch (device globals — allocation-free)
__device__ uint2 g_xh[(size_t)NN * 32];            // projected node features, fp16x4 packed [N,128]
__device__ float g_al[NN * HEADS];                 // alpha_l per node
__device__ float g_ar[NN * HEADS];                 // alpha_r per node
__device__ int   g_cnt[NN];                        // in-degree counters
__device__ int   g_bsrc[(size_t)NN * CAP];         // bucketed src ids
__device__ float g_bex[(size_t)NN * CAP * HEADS];  // bucketed exp(logit) per head
__device__ float g_u[2 * HEADS * IN_CH];           // folded att_l/att_r through Wl
__device__ float g_v[HEADS * EDGE_CH];             // folded att_e through We

// ---- packed fp32x2 helpers ----
__device__ __forceinline__ u64 pack_dup(float a) {
    u64 r; asm("mov.b64 %0,{%1,%1};" : "=l"(r) : "f"(a)); return r;
}
__device__ __forceinline__ void ffma2(u64& d, u64 a, u64 b) {
    asm("fma.rn.f32x2 %0, %1, %2, %0;" : "+l"(d) : "l"(a), "l"(b));
}
__device__ __forceinline__ float2 unpk(u64 v) {
    float2 f; asm("mov.b64 {%0,%1}, %2;" : "=f"(f.x), "=f"(f.y) : "l"(v)); return f;
}

// ---------------------------------------------------------------------------
// K0: fold attention vectors through the weight matrices.
// ---------------------------------------------------------------------------
__global__ void k0_fold(const float* __restrict__ Wl, const float* __restrict__ We,
                        const float* __restrict__ att_l, const float* __restrict__ att_r,
                        const float* __restrict__ att_e) {
    int t = threadIdx.x;
    for (int i = t; i < 2 * HEADS * IN_CH; i += blockDim.x) {
        int side = i / (HEADS * IN_CH);
        int rem = i % (HEADS * IN_CH);
        int h = rem / IN_CH;
        int k = rem % IN_CH;
        const float* att = side ? att_r : att_l;
        float s = 0.f;
        #pragma unroll
        for (int c = 0; c < OUT_CH; c++)
            s += att[h * OUT_CH + c] * Wl[(h * OUT_CH + c) * IN_CH + k];
        g_u[i] = s;
    }
    for (int i = t; i < HEADS * EDGE_CH; i += blockDim.x) {
        int h = i / EDGE_CH;
        int ec = i % EDGE_CH;
        float s = 0.f;
        #pragma unroll
        for (int c = 0; c < OUT_CH; c++)
            s += att_e[h * OUT_CH + c] * We[(h * OUT_CH + c) * EDGE_CH + ec];
        g_v[i] = s;
    }
}

// ---------------------------------------------------------------------------
// KALR: alpha_l/alpha_r via folded u. 8-lane groups, 4 nodes per warp,
// 32 nodes per block, grid = NN/32 = 3125. Also zeros g_cnt.
// ---------------------------------------------------------------------------
__global__ void kalr(const float* __restrict__ x) {
    __shared__ float su[2 * HEADS * IN_CH];   // 1024 floats
    int t = threadIdx.x;
    for (int i = t; i < 1024; i += 256) su[i] = g_u[i];
    if (blockIdx.x < 391) {
        int zi = blockIdx.x * 256 + t;
        if (zi < NN) g_cnt[zi] = 0;
    }
    __syncthreads();

    int warp = t >> 5, lane = t & 31;
    int g = lane >> 3, l8 = lane & 7;
    int node = blockIdx.x * 32 + warp * 4 + g;   // 3125*32 = 100000 exact

    const float4* x4 = (const float4*)x;
    float p[8];
    #pragma unroll
    for (int o = 0; o < 8; o++) p[o] = 0.f;

    #pragma unroll
    for (int c = 0; c < 4; c++) {
        float4 xv = x4[(ll)node * 32 + c * 8 + l8];
        #pragma unroll
        for (int o = 0; o < 8; o++) {
            const float* u = su + o * IN_CH + c * 32 + l8 * 4;
            p[o] += xv.x * u[0] + xv.y * u[1] + xv.z * u[2] + xv.w * u[3];
        }
    }
    #pragma unroll
    for (int o = 0; o < 8; o++) {
        p[o] += __shfl_xor_sync(0xFFFFFFFF, p[o], 1);
        p[o] += __shfl_xor_sync(0xFFFFFFFF, p[o], 2);
        p[o] += __shfl_xor_sync(0xFFFFFFFF, p[o], 4);
    }
    int o = l8;
    float val = p[o];
    int side = o >> 2, h = o & 3;
    if (side == 0) g_al[node * HEADS + h] = val;
    else           g_ar[node * HEADS + h] = val;
}

// ---------------------------------------------------------------------------
// K1: xl = x @ Wl^T, 64 rows/block, 256 threads, 8x4 tile, f32x2 FMA.
// fp32 W+x tiles in smem (proven 98.7us config). Output packed fp16.
// ---------------------------------------------------------------------------
#define WSTRIDE 132
#define XSTRIDE 68

__global__ void k1_gemm(const float* __restrict__ x, const float* __restrict__ Wl) {
    extern __shared__ float sm[];
    float* sWt = sm;                         // [k][j] stride WSTRIDE
    float* sxT = sm + IN_CH * WSTRIDE;       // [k][r] stride XSTRIDE

    int t = threadIdx.x;
    int row0 = blockIdx.x * 64;

    for (int i = t; i < IN_CH * IN_CH; i += 256) {
        int j = i >> 7, k = i & 127;
        sWt[k * WSTRIDE + j] = Wl[i];
    }
    for (int i = t; i < 64 * IN_CH; i += 256) {
        int r = i >> 7, k = i & 127;
        int rr = row0 + r; rr = rr < NN ? rr : NN - 1;
        sxT[k * XSTRIDE + r] = x[(ll)rr * IN_CH + k];
    }
    __syncthreads();

    int rg = t >> 5;
    int cg = t & 31;

    u64 acc[4][4];
    #pragma unroll
    for (int i = 0; i < 4; i++)
        #pragma unroll
        for (int j = 0; j < 4; j++) acc[i][j] = 0ull;

    const float* xbase = sxT + rg * 8;
    const float* wbase = sWt + cg * 4;

    #pragma unroll 4
    for (int k = 0; k < IN_CH; k++) {
        ulonglong2 xa = *(const ulonglong2*)(xbase + k * XSTRIDE);
        ulonglong2 xb = *(const ulonglong2*)(xbase + k * XSTRIDE + 4);
        float4 wv = *(const float4*)(wbase + k * WSTRIDE);
        u64 w0 = pack_dup(wv.x), w1 = pack_dup(wv.y);
        u64 w2 = pack_dup(wv.z), w3 = pack_dup(wv.w);
        ffma2(acc[0][0], xa.x, w0); ffma2(acc[0][1], xa.x, w1);
        ffma2(acc[0][2], xa.x, w2); ffma2(acc[0][3], xa.x, w3);
        ffma2(acc[1][0], xa.y, w0); ffma2(acc[1][1], xa.y, w1);
        ffma2(acc[1][2], xa.y, w2); ffma2(acc[1][3], xa.y, w3);
        ffma2(acc[2][0], xb.x, w0); ffma2(acc[2][1], xb.x, w1);
        ffma2(acc[2][2], xb.x, w2); ffma2(acc[2][3], xb.x, w3);
        ffma2(acc[3][0], xb.y, w0); ffma2(acc[3][1], xb.y, w1);
        ffma2(acc[3][2], xb.y, w2); ffma2(acc[3][3], xb.y, w3);
    }

    #pragma unroll
    for (int rp = 0; rp < 4; rp++) {
        float2 a0 = unpk(acc[rp][0]), a1 = unpk(acc[rp][1]);
        float2 a2 = unpk(acc[rp][2]), a3 = unpk(acc[rp][3]);
        int rA = row0 + rg * 8 + rp * 2;
        union { uint2 u; __half2 h[2]; } P;
        if (rA < NN) {
            P.h[0] = __floats2half2_rn(a0.x, a1.x);
            P.h[1] = __floats2half2_rn(a2.x, a3.x);
            g_xh[(ll)rA * 32 + cg] = P.u;
        }
        if (rA + 1 < NN) {
            P.h[0] = __floats2half2_rn(a0.y, a1.y);
            P.h[1] = __floats2half2_rn(a2.y, a3.y);
            g_xh[(ll)(rA + 1) * 32 + cg] = P.u;
        }
    }
}

// ---------------------------------------------------------------------------
// K2F: fused edge kernel. 2 lanes stream one edge's 32 channels (coalesced),
// shfl reduce, then the even lane assembles the logit, exp, and buckets it.
// ---------------------------------------------------------------------------
__global__ void k2f_edge(const float* __restrict__ edge_attr,
                         const int* __restrict__ ei) {
    __shared__ float sv[HEADS * EDGE_CH];
    int t = threadIdx.x;
    if (t < HEADS * EDGE_CH) sv[t] = g_v[t];
    __syncthreads();

    int eg  = t >> 1;
    int sub = t & 1;
    int e = blockIdx.x * 128 + eg;

    int src = 0, dst = 0;
    if (sub == 0) { src = ei[e]; dst = ei[NE + e]; }

    const float4* ea = (const float4*)edge_attr;
    ll base = (ll)e * 8 + sub * 4;
    float4 v0 = ea[base + 0];
    float4 v1 = ea[base + 1];
    float4 v2 = ea[base + 2];
    float4 v3 = ea[base + 3];

    float acc[HEADS];
    #pragma unroll
    for (int h = 0; h < HEADS; h++) {
        const float* s = sv + h * EDGE_CH + sub * 16;
        float a;
        a  = v0.x * s[0]  + v0.y * s[1]  + v0.z * s[2]  + v0.w * s[3];
        a += v1.x * s[4]  + v1.y * s[5]  + v1.z * s[6]  + v1.w * s[7];
        a += v2.x * s[8]  + v2.y * s[9]  + v2.z * s[10] + v2.w * s[11];
        a += v3.x * s[12] + v3.y * s[13] + v3.z * s[14] + v3.w * s[15];
        acc[h] = a;
    }
    #pragma unroll
    for (int h = 0; h < HEADS; h++)
        acc[h] += __shfl_xor_sync(0xFFFFFFFF, acc[h], 1);

    if (sub == 0) {
        float4 av = ((const float4*)g_al)[src];
        float4 bv = ((const float4*)g_ar)[dst];
        float t0 = acc[0] + av.x + bv.x;
        float t1 = acc[1] + av.y + bv.y;
        float t2 = acc[2] + av.z + bv.z;
        float t3 = acc[3] + av.w + bv.w;
        t0 = fmaxf(t0, 0.f) + NEG_SLOPE * fminf(t0, 0.f);
        t1 = fmaxf(t1, 0.f) + NEG_SLOPE * fminf(t1, 0.f);
        t2 = fmaxf(t2, 0.f) + NEG_SLOPE * fminf(t2, 0.f);
        t3 = fmaxf(t3, 0.f) + NEG_SLOPE * fminf(t3, 0.f);
        float4 ex = make_float4(__expf(t0), __expf(t1), __expf(t2), __expf(t3));

        int pos = atomicAdd(&g_cnt[dst], 1);
        if (pos < CAP) {
            ll b = (ll)dst * CAP + pos;
            g_bsrc[b] = src;
            ((float4*)g_bex)[b] = ex;
        }
    }
}

// ---------------------------------------------------------------------------
// K5: 4 warps per node (quarter buckets), chunk-4 unroll, smem combine.
// 256 threads = 8 warps = 2 nodes/block; grid = NN/2 = 50000 exact.
// ---------------------------------------------------------------------------
__global__ void k5_agg(float* __restrict__ out, const float* __restrict__ bias) {
    __shared__ float sred[2][3][32][5];   // [node][warp-1][lane][5 partials]
    int t = threadIdx.x;
    int warp = t >> 5;
    int nodeL = warp >> 2;
    int sub = warp & 3;
    int node = blockIdx.x * 2 + nodeL;    // 50000*2 = 100000 exact
    int lane = t & 31;
    int h = lane >> 3;

    int cnt = min(g_cnt[node], CAP);
    int lo = (cnt * sub) >> 2;
    int hi = (cnt * (sub + 1)) >> 2;

    const int* bsrc = g_bsrc + (ll)node * CAP;
    const float* bex = g_bex + (ll)node * CAP * HEADS;

    float den = 0.f;
    float ax = 0.f, ay = 0.f, az = 0.f, aw = 0.f;

    int i = lo;
    for (; i + 4 <= hi; i += 4) {
        int s[4]; float w[4]; uint2 xv[4];
        #pragma unroll
        for (int j = 0; j < 4; j++) s[j] = bsrc[i + j];
        #pragma unroll
        for (int j = 0; j < 4; j++) w[j] = bex[(i + j) * HEADS + h];
        #pragma unroll
        for (int j = 0; j < 4; j++) xv[j] = g_xh[(ll)s[j] * 32 + lane];
        #pragma unroll
        for (int j = 0; j < 4; j++) {
            __half2* hp = (__half2*)&xv[j];
            float2 f01 = __half22float2(hp[0]);
            float2 f23 = __half22float2(hp[1]);
            den += w[j];
            ax += w[j] * f01.x; ay += w[j] * f01.y;
            az += w[j] * f23.x; aw += w[j] * f23.y;
        }
    }
    for (; i < hi; i++) {
        int s = bsrc[i];
        float w = bex[i * HEADS + h];
        uint2 xv = g_xh[(ll)s * 32 + lane];
        __half2* hp = (__half2*)&xv;
        float2 f01 = __half22float2(hp[0]);
        float2 f23 = __half22float2(hp[1]);
        den += w;
        ax += w * f01.x; ay += w * f01.y; az += w * f23.x; aw += w * f23.y;
    }

    if (sub) {
        float* r = sred[nodeL][sub - 1][lane];
        r[0] = den; r[1] = ax; r[2] = ay; r[3] = az; r[4] = aw;
    }
    __syncthreads();
    if (sub == 0) {
        #pragma unroll
        for (int p = 0; p < 3; p++) {
            const float* r = sred[nodeL][p][lane];
            den += r[0]; ax += r[1]; ay += r[2]; az += r[3]; aw += r[4];
        }
        float inv = 1.f / (den + EPS);
        float4 b = ((const float4*)bias)[lane];
        float4 o = make_float4(ax * inv + b.x, ay * inv + b.y,
                               az * inv + b.z, aw * inv + b.w);
        ((float4*)out)[(ll)node * 32 + lane] = o;
    }
}

// ---------------------------------------------------------------------------
extern "C" void kernel_launch(void* const* d_in, const int* in_sizes, int n_in,
                              void* d_out, int out_size) {
    const float* x        = (const float*)d_in[0];
    const float* edge_attr= (const float*)d_in[1];
    const float* Wl       = (const float*)d_in[2];
    const float* We       = (const float*)d_in[3];
    const float* att_l    = (const float*)d_in[4];
    const float* att_r    = (const float*)d_in[5];
    const float* att_e    = (const float*)d_in[6];
    const float* bias     = (const float*)d_in[7];
    const int*   ei       = (const int*)d_in[8];
    float* out = (float*)d_out;

    const int k1_smem = (IN_CH * WSTRIDE + IN_CH * XSTRIDE) * (int)sizeof(float);
    static cudaStream_t s1 = nullptr;
    static cudaEvent_t evFork = nullptr, evJoin = nullptr;
    if (!s1) {
        cudaFuncSetAttribute(k1_gemm, cudaFuncAttributeMaxDynamicSharedMemorySize, k1_smem);
        cudaStreamCreateWithFlags(&s1, cudaStreamNonBlocking);
        cudaEventCreateWithFlags(&evFork, cudaEventDisableTiming);
        cudaEventCreateWithFlags(&evJoin, cudaEventDisableTiming);
    }

    // default: k1 ----------------------------------------\
    //                                                      join -> k5
    // s1:      k0 -> kalr -> k2f -------------------------/
    cudaEventRecord(evFork, 0);
    cudaStreamWaitEvent(s1, evFork, 0);
    k0_fold<<<1, 256, 0, s1>>>(Wl, We, att_l, att_r, att_e);
    kalr<<<NN / 32, 256, 0, s1>>>(x);                      // al/ar + zero g_cnt
    k2f_edge<<<NE / 128, 256, 0, s1>>>(edge_attr, ei);
    cudaEventRecord(evJoin, s1);
    k1_gemm<<<(NN + 63) / 64, 256, k1_smem>>>(x, Wl);
    cudaStreamWaitEvent((cudaStream_t)0, evJoin, 0);
    k5_agg<<<NN / 2, 256>>>(out, bias);
}